// round 8
// baseline (speedup 1.0000x reference)
#include <cuda_runtime.h>
#include <cuda_bf16.h>
#include <mma.h>
#include <cstdint>

using namespace nvcuda;

// ============================================================================
// y[M,N] = fq(x*sx)[M,K] @ fq(w*sw)[N,K]^T / (sx*sw) + bias, bf16-rounded
// Harness materializes ALL tensors as float32 (evidence: rounds 2-7 rel_err
// pattern). I/O in f32; outputs are bf16-rounded values stored as f32.
// ============================================================================
#define GM 8192
#define GN 4096
#define GK 4096

#define BM 128
#define BN 128
#define BKE 64                      // bf16 elems per K chunk
#define K_CHUNKS (GK / BKE)         // 64
#define STAGES 4
#define PITCH 80                    // smem row pitch in elems (160 B)
#define TILE_B (128 * PITCH * 2)    // 20480 B per operand tile
#define STAGE_B (2 * TILE_B)        // 40960
#define SMEM_TOTAL (STAGES * STAGE_B)  // 163840

// quantized operands as bf16 (e4m3 values are exact in bf16), row-major
__device__ __align__(128) __nv_bfloat16 g_Aq[(size_t)GM * GK];
__device__ __align__(128) __nv_bfloat16 g_Bq[(size_t)GN * GK];

// ============================================================================
// helpers
// ============================================================================
__device__ __forceinline__ uint32_t smem_to_u32(const void* p) {
    uint32_t a;
    asm("{ .reg .u64 t; cvta.to.shared.u64 t, %1; cvt.u32.u64 %0, t; }" : "=r"(a) : "l"(p));
    return a;
}
__device__ __forceinline__ void cp_async16(uint32_t dst_smem, const void* src) {
    asm volatile("cp.async.cg.shared.global [%0], [%1], 16;"
                 :: "r"(dst_smem), "l"(src) : "memory");
}
#define CP_COMMIT() asm volatile("cp.async.commit_group;" ::: "memory")
#define CP_WAIT2()  asm volatile("cp.async.wait_group 2;" ::: "memory")
#define CP_WAIT0()  asm volatile("cp.async.wait_group 0;" ::: "memory")

// ----------------------------------------------------------------------------
// Exact reference fake-quant (E4M3: clip 448, 3 mantissa bits, min exp -6):
//   e = max(floor(log2|clip|), -6); step = 2^(e-3); q = rint(clip/step)*step
// ----------------------------------------------------------------------------
__device__ __forceinline__ float fake_quant_e4m3(float y) {
    float yc = fminf(fmaxf(y, -448.0f), 448.0f);
    float mag = fabsf(yc);
    if (mag == 0.0f) return 0.0f;
    int e = (int)((__float_as_uint(mag) >> 23) & 0xFF) - 127;
    if (e < -6) e = -6;
    float stepinv = __int_as_float((uint32_t)(127 + 3 - e) << 23);  // 2^(3-e)
    float step    = __int_as_float((uint32_t)(127 - 3 + e) << 23);  // 2^(e-3)
    return rintf(yc * stepinv) * step;
}

// ============================================================================
// Quantization: f32 in -> scale -> exact e4m3 fake-quant -> bf16 scratch
// ============================================================================
__global__ void quant_kernel(const float* __restrict__ src,
                             const float* __restrict__ scale_p,
                             __nv_bfloat16* __restrict__ dst, int total8) {
    int idx = blockIdx.x * blockDim.x + threadIdx.x;
    if (idx >= total8) return;
    const float s = scale_p[0];
    size_t e0 = (size_t)idx * 8;
    float4 v0 = *reinterpret_cast<const float4*>(src + e0);
    float4 v1 = *reinterpret_cast<const float4*>(src + e0 + 4);
    float f[8] = {v0.x, v0.y, v0.z, v0.w, v1.x, v1.y, v1.z, v1.w};
    uint32_t o[4];
#pragma unroll
    for (int i = 0; i < 4; i++) {
        float q0 = fake_quant_e4m3(f[2 * i] * s);
        float q1 = fake_quant_e4m3(f[2 * i + 1] * s);
        __nv_bfloat162 ob = __floats2bfloat162_rn(q0, q1);   // exact for e4m3 values
        o[i] = *reinterpret_cast<uint32_t*>(&ob);
    }
    *reinterpret_cast<uint4*>(dst + e0) = make_uint4(o[0], o[1], o[2], o[3]);
}

// ============================================================================
// wmma GEMM: 128x128 CTA tile, 8 warps (64x32 each), 4-stage cp.async pipeline.
// Epilogue: dequant + bias -> bf16 RNE -> store as f32.
// ============================================================================
__global__ void __launch_bounds__(256, 1) gemm_kernel(
    const float* __restrict__ bias,
    const float* __restrict__ xs, const float* __restrict__ ws,
    float* __restrict__ out) {
    extern __shared__ __align__(1024) char smem[];
    const uint32_t smem_u = smem_to_u32(smem);
    const int tid = threadIdx.x;
    const int w = tid >> 5, l = tid & 31;
    const int wm = (w >> 2) * 64;   // 0 or 64
    const int wn = (w & 3) * 32;    // 0,32,64,96
    const int nt = blockIdx.x, mt = blockIdx.y;

    const __nv_bfloat16* Ag = g_Aq + (size_t)(mt * BM) * GK;
    const __nv_bfloat16* Bg = g_Bq + (size_t)(nt * BN) * GK;

    auto load_stage = [&](int s, int kc) {
        const uint32_t sa = smem_u + s * STAGE_B;
        const uint32_t sb = sa + TILE_B;
#pragma unroll
        for (int i = 0; i < 4; i++) {
            int c = tid + i * 256;
            int row = c >> 3, cb = c & 7;
            cp_async16(sa + row * (PITCH * 2) + cb * 16,
                       Ag + (size_t)row * GK + kc * BKE + cb * 8);
        }
#pragma unroll
        for (int i = 0; i < 4; i++) {
            int c = tid + i * 256;
            int row = c >> 3, cb = c & 7;
            cp_async16(sb + row * (PITCH * 2) + cb * 16,
                       Bg + (size_t)row * GK + kc * BKE + cb * 8);
        }
        CP_COMMIT();
    };

    wmma::fragment<wmma::accumulator, 16, 16, 16, float> cf[4][2];
#pragma unroll
    for (int mi = 0; mi < 4; mi++)
#pragma unroll
        for (int ni = 0; ni < 2; ni++)
            wmma::fill_fragment(cf[mi][ni], 0.0f);

    load_stage(0, 0);
    load_stage(1, 1);
    load_stage(2, 2);

#pragma unroll 1
    for (int kc = 0; kc < K_CHUNKS; ++kc) {
        CP_WAIT2();
        __syncthreads();
        if (kc + 3 < K_CHUNKS) load_stage((kc + 3) & (STAGES - 1), kc + 3);

        const char* sp = smem + (kc & (STAGES - 1)) * STAGE_B;
        const __nv_bfloat16* As = reinterpret_cast<const __nv_bfloat16*>(sp);
        const __nv_bfloat16* Bs = reinterpret_cast<const __nv_bfloat16*>(sp + TILE_B);

#pragma unroll
        for (int ks = 0; ks < 4; ks++) {
            wmma::fragment<wmma::matrix_a, 16, 16, 16, __nv_bfloat16, wmma::row_major> af[4];
            wmma::fragment<wmma::matrix_b, 16, 16, 16, __nv_bfloat16, wmma::col_major> bf[2];
#pragma unroll
            for (int mi = 0; mi < 4; mi++)
                wmma::load_matrix_sync(af[mi], As + (wm + mi * 16) * PITCH + ks * 16, PITCH);
#pragma unroll
            for (int ni = 0; ni < 2; ni++)
                wmma::load_matrix_sync(bf[ni], Bs + (wn + ni * 16) * PITCH + ks * 16, PITCH);
#pragma unroll
            for (int mi = 0; mi < 4; mi++)
#pragma unroll
                for (int ni = 0; ni < 2; ni++)
                    wmma::mma_sync(cf[mi][ni], af[mi], bf[ni], cf[mi][ni]);
        }
        __syncthreads();
    }
    CP_WAIT0();
    __syncthreads();   // pipeline drained; smem reusable as scratch

    // ---- epilogue: per-warp f32 scratch, dequant + bias, bf16-rounded f32 ----
    float* scratch = reinterpret_cast<float*>(smem) + w * 256;   // 16x16 per warp
    const float inv = 1.0f / (xs[0] * ws[0]);
    const int r = l >> 1, cc = (l & 1) * 8;

#pragma unroll
    for (int mi = 0; mi < 4; mi++) {
#pragma unroll
        for (int ni = 0; ni < 2; ni++) {
            wmma::store_matrix_sync(scratch, cf[mi][ni], 16, wmma::mem_row_major);
            __syncwarp();
            const int gr = mt * BM + wm + mi * 16 + r;
            const int gc = nt * BN + wn + ni * 16 + cc;
            float o[8];
#pragma unroll
            for (int j = 0; j < 8; j++) {
                float f = scratch[r * 16 + cc + j] * inv + bias[gc + j];
                o[j] = __bfloat162float(__float2bfloat16_rn(f));   // reference's bf16 cast
            }
            float* orow = out + (size_t)gr * GN + gc;
            *reinterpret_cast<float4*>(orow)     = make_float4(o[0], o[1], o[2], o[3]);
            *reinterpret_cast<float4*>(orow + 4) = make_float4(o[4], o[5], o[6], o[7]);
            __syncwarp();
        }
    }
}

// ============================================================================
// kernel_launch — inputs identified by element count (dtype-independent)
// ============================================================================
extern "C" void kernel_launch(void* const* d_in, const int* in_sizes, int n_in,
                              void* d_out, int out_size) {
    const float* x = nullptr;
    const float* wgt = nullptr;
    const float* bias = nullptr;
    const float* scales[3] = {nullptr, nullptr, nullptr};
    int ns = 0;
    for (int i = 0; i < n_in; i++) {
        const int sz = in_sizes[i];
        if (sz == GM * GK)      x    = (const float*)d_in[i];
        else if (sz == GN * GK) wgt  = (const float*)d_in[i];
        else if (sz == GN)      bias = (const float*)d_in[i];
        else if (sz == 1 && ns < 3) scales[ns++] = (const float*)d_in[i];
    }
    const float* xs = scales[0];   // x_scale (first size-1 input)
    const float* ws = scales[1];   // w_scale (second size-1 input)
    float* out = (float*)d_out;

    __nv_bfloat16* aq; cudaGetSymbolAddress((void**)&aq, g_Aq);
    __nv_bfloat16* bq; cudaGetSymbolAddress((void**)&bq, g_Bq);

    {
        const int total8 = GM * GK / 8;
        quant_kernel<<<total8 / 256, 256>>>(x, xs, aq, total8);
    }
    {
        const int total8 = GN * GK / 8;
        quant_kernel<<<total8 / 256, 256>>>(wgt, ws, bq, total8);
    }

    cudaFuncSetAttribute(gemm_kernel, cudaFuncAttributeMaxDynamicSharedMemorySize, SMEM_TOTAL);
    dim3 grid(GN / BN, GM / BM);   // (32, 64) = 2048 CTAs
    gemm_kernel<<<grid, 256, SMEM_TOTAL>>>(bias, xs, ws, out);
}

// round 9
// speedup vs baseline: 2.7602x; 2.7602x over previous
#include <cuda_runtime.h>
#include <cuda_bf16.h>
#include <cuda_fp8.h>
#include <cstdint>

// ============================================================================
// y[M,N] = fq(x*sx)[M,K] @ fq(w*sw)[N,K]^T / (sx*sw) + bias, bf16-rounded,
// stored as f32 (harness materializes every tensor as float32).
// GEMM: fp8 mma.sync.m16n8k32 (layout validated by rounds 2==3 equivalence).
// ============================================================================
#define GM 8192
#define GN 4096
#define GK 4096

#define BM 128
#define BN 256
#define BK 128                     // fp8 bytes (= elems) per K chunk
#define K_CHUNKS (GK / BK)         // 32
#define STAGES 4

#define A_BYTES (BM * BK)          // 16384
#define B_BYTES (BN * BK)          // 32768
#define STAGE_BYTES (A_BYTES + B_BYTES)      // 49152
#define SMEM_TOTAL (STAGES * STAGE_BYTES)    // 196608

// fp8 scratch, plain row-major [M][K] / [N][K]
__device__ __align__(128) unsigned char g_Aq[(size_t)GM * GK];
__device__ __align__(128) unsigned char g_Bq[(size_t)GN * GK];

// ============================================================================
// helpers
// ============================================================================
__device__ __forceinline__ uint32_t smem_to_u32(const void* p) {
    uint32_t a;
    asm("{ .reg .u64 t; cvta.to.shared.u64 t, %1; cvt.u32.u64 %0, t; }" : "=r"(a) : "l"(p));
    return a;
}
__device__ __forceinline__ void cp_async16(uint32_t dst_smem, const void* src) {
    asm volatile("cp.async.cg.shared.global [%0], [%1], 16;"
                 :: "r"(dst_smem), "l"(src) : "memory");
}
#define CP_COMMIT() asm volatile("cp.async.commit_group;" ::: "memory")
#define CP_WAIT2()  asm volatile("cp.async.wait_group 2;" ::: "memory")
#define CP_WAIT0()  asm volatile("cp.async.wait_group 0;" ::: "memory")

__device__ __forceinline__ void ldmatrix_x4(uint32_t& r0, uint32_t& r1,
                                            uint32_t& r2, uint32_t& r3, uint32_t addr) {
    asm volatile("ldmatrix.sync.aligned.m8n8.x4.shared.b16 {%0,%1,%2,%3}, [%4];"
                 : "=r"(r0), "=r"(r1), "=r"(r2), "=r"(r3) : "r"(addr));
}

__device__ __forceinline__ void mma_e4m3(float* d, const uint32_t* a,
                                         uint32_t b0, uint32_t b1) {
    asm volatile(
        "mma.sync.aligned.m16n8k32.row.col.f32.e4m3.e4m3.f32 "
        "{%0,%1,%2,%3}, {%4,%5,%6,%7}, {%8,%9}, {%0,%1,%2,%3};"
        : "+f"(d[0]), "+f"(d[1]), "+f"(d[2]), "+f"(d[3])
        : "r"(a[0]), "r"(a[1]), "r"(a[2]), "r"(a[3]), "r"(b0), "r"(b1));
}

// ----------------------------------------------------------------------------
// Exact reference fake-quant (E4M3: clip 448, 3 mantissa bits, min exp -6).
// Verified bit-exact vs reference in round 8 (rel_err = 0.0).
// ----------------------------------------------------------------------------
__device__ __forceinline__ float fake_quant_e4m3(float y) {
    float yc = fminf(fmaxf(y, -448.0f), 448.0f);
    float mag = fabsf(yc);
    if (mag == 0.0f) return 0.0f;
    int e = (int)((__float_as_uint(mag) >> 23) & 0xFF) - 127;
    if (e < -6) e = -6;
    float stepinv = __int_as_float((uint32_t)(127 + 3 - e) << 23);  // 2^(3-e)
    float step    = __int_as_float((uint32_t)(127 - 3 + e) << 23);  // 2^(e-3)
    return rintf(yc * stepinv) * step;
}

// ============================================================================
// Quantization: f32 in -> exact fake-quant -> e4m3 byte (exact conversion of
// an exactly-representable value) -> fp8 scratch, row-major.
// ============================================================================
__global__ void quant_kernel(const float* __restrict__ src,
                             const float* __restrict__ scale_p,
                             unsigned char* __restrict__ dst, int total8) {
    int idx = blockIdx.x * blockDim.x + threadIdx.x;
    if (idx >= total8) return;
    const float s = scale_p[0];
    size_t e0 = (size_t)idx * 8;
    float4 v0 = *reinterpret_cast<const float4*>(src + e0);
    float4 v1 = *reinterpret_cast<const float4*>(src + e0 + 4);
    float f[8] = {v0.x, v0.y, v0.z, v0.w, v1.x, v1.y, v1.z, v1.w};
    uint64_t out8 = 0;
#pragma unroll
    for (int i = 0; i < 8; i++) {
        float q = fake_quant_e4m3(f[i] * s);
        uint8_t b = __nv_cvt_float_to_fp8(q, __NV_SATFINITE, __NV_E4M3);
        out8 |= (uint64_t)b << (8 * i);
    }
    *reinterpret_cast<uint64_t*>(dst + e0) = out8;
}

// ============================================================================
// FP8 GEMM: 128x256 CTA tile, 8 warps (64x64 each), 4-stage cp.async pipeline,
// mma.sync m16n8k32 e4m3, fused dequant + bias + bf16-round, f32 stores.
// ============================================================================
__global__ void __launch_bounds__(256, 1) gemm_kernel(
    const float* __restrict__ bias,
    const float* __restrict__ xs, const float* __restrict__ ws,
    float* __restrict__ out) {
    extern __shared__ __align__(128) char smem[];
    const uint32_t smem_base = smem_to_u32(smem);
    const int tid = threadIdx.x;
    const int w = tid >> 5, l = tid & 31;
    const int warp_m = (w >> 2) * 64;     // 0 or 64
    const int warp_n = (w & 3) * 64;      // 0,64,128,192
    const int nt = blockIdx.x, mt = blockIdx.y;

    const unsigned char* Ag = g_Aq + (size_t)(mt * BM) * GK;
    const unsigned char* Bg = g_Bq + (size_t)(nt * BN) * GK;

    auto load_stage = [&](int s, int kc) {
        const uint32_t sa = smem_base + s * STAGE_BYTES;
        const uint32_t sb = sa + A_BYTES;
        // A: 1024 16B chunks (128 rows x 8)
#pragma unroll
        for (int i = 0; i < 4; i++) {
            int c = tid + i * 256;
            int row = c >> 3, cb = c & 7;
            cp_async16(sa + row * 128 + ((cb ^ (row & 7)) << 4),
                       Ag + (size_t)row * GK + kc * BK + cb * 16);
        }
        // B: 2048 16B chunks (256 rows x 8)
#pragma unroll
        for (int i = 0; i < 8; i++) {
            int c = tid + i * 256;
            int row = c >> 3, cb = c & 7;
            cp_async16(sb + row * 128 + ((cb ^ (row & 7)) << 4),
                       Bg + (size_t)row * GK + kc * BK + cb * 16);
        }
        CP_COMMIT();
    };

    // accumulators: [mi 0..3][n8-tile 0..7][4]
    float d[4][8][4];
#pragma unroll
    for (int i = 0; i < 4; i++)
#pragma unroll
        for (int j = 0; j < 8; j++)
#pragma unroll
            for (int q = 0; q < 4; q++) d[i][j][q] = 0.0f;

    load_stage(0, 0);
    load_stage(1, 1);
    load_stage(2, 2);

    const int lr = l & 15;        // ldmatrix row-within-16
    const int lk = l >> 4;        // ldmatrix k-half (16B group select)

#pragma unroll 1
    for (int kc = 0; kc < K_CHUNKS; ++kc) {
        CP_WAIT2();
        __syncthreads();
        if (kc + 3 < K_CHUNKS) load_stage((kc + 3) & (STAGES - 1), kc + 3);

        const int s = kc & (STAGES - 1);
        const uint32_t sa = smem_base + s * STAGE_BYTES;
        const uint32_t sb = sa + A_BYTES;

#pragma unroll
        for (int ks = 0; ks < 4; ++ks) {    // 4 x (k=32 fp8) per 128B chunk
            uint32_t a[4][4], bf[4][4];
            const int kg = ks * 2 + lk;     // 16B group index (0..7)
#pragma unroll
            for (int mi = 0; mi < 4; mi++) {
                const int r = warp_m + mi * 16 + lr;
                ldmatrix_x4(a[mi][0], a[mi][1], a[mi][2], a[mi][3],
                            sa + r * 128 + (((kg ^ (r & 7)) & 7) << 4));
            }
#pragma unroll
            for (int j = 0; j < 4; j++) {
                const int r = warp_n + j * 16 + lr;
                ldmatrix_x4(bf[j][0], bf[j][1], bf[j][2], bf[j][3],
                            sb + r * 128 + (((kg ^ (r & 7)) & 7) << 4));
            }
#pragma unroll
            for (int mi = 0; mi < 4; mi++)
#pragma unroll
                for (int nj = 0; nj < 8; nj++) {
                    const int j = nj >> 1, h = nj & 1;
                    mma_e4m3(d[mi][nj], a[mi], bf[j][h], bf[j][2 + h]);
                }
        }
        __syncthreads();
    }
    CP_WAIT0();

    // ---- epilogue: dequant + bias, bf16-round, f32 stores ----
    const float inv = 1.0f / (xs[0] * ws[0]);
    const int mrow = mt * BM + warp_m + (l >> 2);
    const int ncol0 = nt * BN + warp_n + 2 * (l & 3);

#pragma unroll
    for (int nj = 0; nj < 8; nj++) {
        const int n = ncol0 + nj * 8;
        const float b0 = bias[n];
        const float b1 = bias[n + 1];
#pragma unroll
        for (int mi = 0; mi < 4; mi++) {
            const int m0 = mrow + mi * 16;
            float f0 = __bfloat162float(__float2bfloat16_rn(d[mi][nj][0] * inv + b0));
            float f1 = __bfloat162float(__float2bfloat16_rn(d[mi][nj][1] * inv + b1));
            float f2 = __bfloat162float(__float2bfloat16_rn(d[mi][nj][2] * inv + b0));
            float f3 = __bfloat162float(__float2bfloat16_rn(d[mi][nj][3] * inv + b1));
            *reinterpret_cast<float2*>(out + (size_t)m0 * GN + n) = make_float2(f0, f1);
            *reinterpret_cast<float2*>(out + (size_t)(m0 + 8) * GN + n) = make_float2(f2, f3);
        }
    }
}

// ============================================================================
// kernel_launch — inputs identified by element count
// ============================================================================
extern "C" void kernel_launch(void* const* d_in, const int* in_sizes, int n_in,
                              void* d_out, int out_size) {
    const float* x = nullptr;
    const float* wgt = nullptr;
    const float* bias = nullptr;
    const float* scales[3] = {nullptr, nullptr, nullptr};
    int ns = 0;
    for (int i = 0; i < n_in; i++) {
        const int sz = in_sizes[i];
        if (sz == GM * GK)      x    = (const float*)d_in[i];
        else if (sz == GN * GK) wgt  = (const float*)d_in[i];
        else if (sz == GN)      bias = (const float*)d_in[i];
        else if (sz == 1 && ns < 3) scales[ns++] = (const float*)d_in[i];
    }
    const float* xs = scales[0];   // x_scale (first size-1 input)
    const float* ws = scales[1];   // w_scale (second size-1 input)
    float* out = (float*)d_out;

    unsigned char* aq; cudaGetSymbolAddress((void**)&aq, g_Aq);
    unsigned char* bq; cudaGetSymbolAddress((void**)&bq, g_Bq);

    {
        const int total8 = GM * GK / 8;
        quant_kernel<<<total8 / 256, 256>>>(x, xs, aq, total8);
    }
    {
        const int total8 = GN * GK / 8;
        quant_kernel<<<total8 / 256, 256>>>(wgt, ws, bq, total8);
    }

    cudaFuncSetAttribute(gemm_kernel, cudaFuncAttributeMaxDynamicSharedMemorySize, SMEM_TOTAL);
    dim3 grid(GN / BN, GM / BM);   // (16, 64) = 1024 CTAs
    gemm_kernel<<<grid, 256, SMEM_TOTAL>>>(bias, xs, ws, out);
}